// round 13
// baseline (speedup 1.0000x reference)
#include <cuda_runtime.h>
#include <cuda_bf16.h>
#include <cstdint>
#include <math.h>

#define NB 8192
#define ND 128
#define C_ALPHA 2.0f
#define C_BETA 50.0f
#define C_BASE 0.5f
#define C_MARGIN 0.1f

// ---------------------------------------------------------------------------
// Scratch (allocation-free rule: __device__ globals)
// ---------------------------------------------------------------------------
__device__ float g_sim[(size_t)NB * NB];           // full matrix (both triangles)
__device__ __nv_bfloat16 g_Ehi[(size_t)NB * ND];
__device__ __nv_bfloat16 g_Elo[(size_t)NB * ND];
__device__ float g_loss_sum;
__device__ int   g_valid_cnt;
__device__ unsigned g_done;

__device__ __forceinline__ uint32_t smem_u32(const void* p) {
    uint32_t a;
    asm("{ .reg .u64 t; cvta.to.shared.u64 t, %1; cvt.u32.u64 %0, t; }" : "=r"(a) : "l"(p));
    return a;
}

#define LDMATRIX_X4(r0, r1, r2, r3, addr)                                      \
    asm volatile("ldmatrix.sync.aligned.m8n8.x4.shared.b16 {%0,%1,%2,%3}, [%4];" \
                 : "=r"(r0), "=r"(r1), "=r"(r2), "=r"(r3) : "r"(addr))
#define LDMATRIX_X2(r0, r1, addr)                                              \
    asm volatile("ldmatrix.sync.aligned.m8n8.x2.shared.b16 {%0,%1}, [%2];"     \
                 : "=r"(r0), "=r"(r1) : "r"(addr))
#define MMA16816(c, a, b)                                                      \
    asm volatile("mma.sync.aligned.m16n8k16.row.col.f32.bf16.bf16.f32 "        \
                 "{%0,%1,%2,%3}, {%4,%5,%6,%7}, {%8,%9}, {%0,%1,%2,%3};"       \
                 : "+f"((c)[0]), "+f"((c)[1]), "+f"((c)[2]), "+f"((c)[3])      \
                 : "r"((a)[0]), "r"((a)[1]), "r"((a)[2]), "r"((a)[3]),         \
                   "r"((b)[0]), "r"((b)[1]))

__device__ __forceinline__ void tri_decode(int t, int& by, int& bx) {
    int rem = t, y = 0;
    while (rem >= (NB / 128) - y) { rem -= (NB / 128) - y; y++; }
    by = y; bx = y + rem;
}

#define NTILE (NB / 128)
#define NTRI (NTILE * (NTILE + 1) / 2)    // 2080

// ---------------------------------------------------------------------------
// Kernel 0: split fp32 -> bf16 hi/lo, reset scalar accumulators
// ---------------------------------------------------------------------------
__global__ __launch_bounds__(256) void split_kernel(const float* __restrict__ E) {
    int i = blockIdx.x * 256 + threadIdx.x;
    if (i == 0) { g_loss_sum = 0.0f; g_valid_cnt = 0; g_done = 0u; }
    float x = E[i];
    __nv_bfloat16 h = __float2bfloat16(x);
    g_Ehi[i] = h;
    g_Elo[i] = __float2bfloat16(x - __bfloat162float(h));
}

// ---------------------------------------------------------------------------
// Kernel 1: triangular-grid GEMM (round-5 loader: plain uint4 ld->st),
// stores BOTH triangles (direct + transposed via SMEM stage).
// ---------------------------------------------------------------------------
#define PAD 8
#define LDT (ND + PAD)                    // 136 bf16 per row
#define ROWB (LDT * 2)                    // 272 B
#define OFF_AHI 0
#define OFF_ALO (OFF_AHI + 128 * ROWB)
#define OFF_BHI (OFF_ALO + 128 * ROWB)
#define OFF_BLO (OFF_BHI + 128 * ROWB)
#define GEMM_SMEM (OFF_BLO + 128 * ROWB)  // 139264
#define TLD 132                           // fp32 transpose-stage stride

__device__ __forceinline__ void gemm_pass(float (&acc)[4][4][4], uint32_t Ab, uint32_t Bb,
                                          int mbase, int nbase, int arow, int acol,
                                          int brow, int bcol) {
#pragma unroll
    for (int k0 = 0; k0 < ND; k0 += 16) {
        uint32_t a[4][4], b[4][2];
#pragma unroll
        for (int mi = 0; mi < 4; mi++) {
            uint32_t ad = Ab + ((mbase + mi * 16 + arow) * LDT + k0 + acol) * 2;
            LDMATRIX_X4(a[mi][0], a[mi][1], a[mi][2], a[mi][3], ad);
        }
#pragma unroll
        for (int ni = 0; ni < 4; ni++) {
            uint32_t bd = Bb + ((nbase + ni * 8 + brow) * LDT + k0 + bcol) * 2;
            LDMATRIX_X2(b[ni][0], b[ni][1], bd);
        }
#pragma unroll
        for (int mi = 0; mi < 4; mi++)
#pragma unroll
            for (int ni = 0; ni < 4; ni++)
                MMA16816(acc[mi][ni], a[mi], b[ni]);
    }
}

__global__ __launch_bounds__(256, 1) void gemm_mma_kernel() {
    int by, bx;
    tri_decode(blockIdx.x, by, bx);

    extern __shared__ char smem[];
    const uint32_t sbase = smem_u32(smem);
    const int tid  = threadIdx.x;
    const int wid  = tid >> 5;
    const int lane = tid & 31;
    const int bm = by * 128;
    const int bn = bx * 128;
    const bool diag = (bx == by);

    // ---- plain uint4 tile loads (round-5 validated path) ----
    for (int t = tid; t < 2048; t += 256) {
        const int r = t >> 4;
        const int c = t & 15;
        const uint32_t so = (uint32_t)r * ROWB + c * 16;
        const size_t ga = (size_t)(bm + r) * ND + c * 8;
        *(uint4*)(smem + OFF_AHI + so) = *(const uint4*)(g_Ehi + ga);
        *(uint4*)(smem + OFF_ALO + so) = *(const uint4*)(g_Elo + ga);
        if (!diag) {
            const size_t gb = (size_t)(bn + r) * ND + c * 8;
            *(uint4*)(smem + OFF_BHI + so) = *(const uint4*)(g_Ehi + gb);
            *(uint4*)(smem + OFF_BLO + so) = *(const uint4*)(g_Elo + gb);
        }
    }
    __syncthreads();

    const int warp_m = wid >> 2;
    const int warp_n = wid & 3;
    const int mbase = warp_m * 64;
    const int nbase = warp_n * 32;
    const int arow = ((lane >> 3) & 1) * 8 + (lane & 7);
    const int acol = ((lane >> 4) & 1) * 8;
    const int brow = lane & 7;
    const int bcol = ((lane >> 3) & 1) * 8;

    float acc[4][4][4];
#pragma unroll
    for (int mi = 0; mi < 4; mi++)
#pragma unroll
        for (int ni = 0; ni < 4; ni++)
#pragma unroll
            for (int q = 0; q < 4; q++) acc[mi][ni][q] = 0.0f;

    const uint32_t aHi = sbase + OFF_AHI;
    const uint32_t aLo = sbase + OFF_ALO;
    const uint32_t bHi = diag ? aHi : sbase + OFF_BHI;
    const uint32_t bLo = diag ? aLo : sbase + OFF_BLO;

    gemm_pass(acc, aHi, bHi, mbase, nbase, arow, acol, brow, bcol);   // hi*hi
    gemm_pass(acc, aHi, bLo, mbase, nbase, arow, acol, brow, bcol);   // hi*lo
    gemm_pass(acc, aLo, bHi, mbase, nbase, arow, acol, brow, bcol);   // lo*hi

    // ---- direct store ----
    const int g   = lane >> 2;
    const int tig = lane & 3;
#pragma unroll
    for (int mi = 0; mi < 4; mi++) {
        const size_t row0 = (size_t)(bm + mbase + mi * 16 + g);
        const size_t row1 = row0 + 8;
#pragma unroll
        for (int ni = 0; ni < 4; ni++) {
            const int col = bn + nbase + ni * 8 + tig * 2;
            *(float2*)(g_sim + row0 * NB + col) = make_float2(acc[mi][ni][0], acc[mi][ni][1]);
            *(float2*)(g_sim + row1 * NB + col) = make_float2(acc[mi][ni][2], acc[mi][ni][3]);
        }
    }

    // ---- transposed store for off-diagonal tiles (SMEM stage) ----
    if (!diag) {
        __syncthreads();               // operand reads done; reuse smem
        float* st = (float*)smem;      // [128][TLD]
#pragma unroll
        for (int mi = 0; mi < 4; mi++) {
            const int r0 = mbase + mi * 16 + g;
#pragma unroll
            for (int ni = 0; ni < 4; ni++) {
                const int c0 = nbase + ni * 8 + tig * 2;
                st[(c0 + 0) * TLD + r0]     = acc[mi][ni][0];
                st[(c0 + 1) * TLD + r0]     = acc[mi][ni][1];
                st[(c0 + 0) * TLD + r0 + 8] = acc[mi][ni][2];
                st[(c0 + 1) * TLD + r0 + 8] = acc[mi][ni][3];
            }
        }
        __syncthreads();
        for (int t = tid; t < 128 * 32; t += 256) {
            const int r  = t >> 5;
            const int c4 = (t & 31) * 4;
            float4 v = *(float4*)(st + r * TLD + c4);
            *(float4*)(g_sim + (size_t)(bn + r) * NB + bm + c4) = v;
        }
    }
}

// ---------------------------------------------------------------------------
// Kernel 2: per-row mining + loss. 512 threads, 8 rows/CTA; row + labels in
// registers; warp-shuffle final reduces; separate pass-1/pass-2 buffers
// (fewer syncs); per-CTA loss accumulation; last-CTA finalize.
// validity: anyPos<=>pmin<inf, anyNeg<=>nmax>-inf, hardPos<=>psum>0,
// hardNeg<=>nsum>0 (nmax elem is hard & above cutoff whenever any is).
// ---------------------------------------------------------------------------
#define RK_ROWS 8

__global__ __launch_bounds__(512, 2) void row_kernel(const int* __restrict__ labels,
                                                     float* __restrict__ out) {
    __shared__ float bufA[16], bufB[16];   // pass-1 (extrema)
    __shared__ float bufC[16], bufD[16];   // pass-2 (sums)
    __shared__ float s_a, s_b;

    const int tid  = threadIdx.x;
    const int lane = tid & 31;
    const int wid  = tid >> 5;
    const int i0   = blockIdx.x * RK_ROWS;

    int4 lab[4];
#pragma unroll
    for (int q = 0; q < 4; q++) lab[q] = ((const int4*)labels)[q * 512 + tid];

    float loss_acc = 0.0f;
    int   cnt_acc  = 0;

    for (int r = 0; r < RK_ROWS; r++) {
        const int i  = i0 + r;
        const int li = __ldg(labels + i);

        float4 sv[4];
        const float4* row4 = (const float4*)(g_sim + (size_t)i * NB);
#pragma unroll
        for (int q = 0; q < 4; q++) sv[q] = row4[q * 512 + tid];

        // ---- pass 1: extrema ----
        float pmin = INFINITY, nmax = -INFINITY;
#pragma unroll
        for (int q = 0; q < 4; q++) {
            const int j0 = (q * 512 + tid) * 4;
            const float s[4] = {sv[q].x, sv[q].y, sv[q].z, sv[q].w};
            const int   l[4] = {lab[q].x, lab[q].y, lab[q].z, lab[q].w};
#pragma unroll
            for (int e = 0; e < 4; e++) {
                if (l[e] == li) { if (j0 + e != i) pmin = fminf(pmin, s[e]); }
                else nmax = fmaxf(nmax, s[e]);
            }
        }
#pragma unroll
        for (int o = 16; o; o >>= 1) {
            pmin = fminf(pmin, __shfl_xor_sync(0xFFFFFFFFu, pmin, o));
            nmax = fmaxf(nmax, __shfl_xor_sync(0xFFFFFFFFu, nmax, o));
        }
        if (lane == 0) { bufA[wid] = pmin; bufB[wid] = nmax; }
        __syncthreads();
        if (wid == 0) {
            float a = bufA[lane & 15];
            float m = bufB[lane & 15];
#pragma unroll
            for (int o = 8; o; o >>= 1) {
                a = fminf(a, __shfl_xor_sync(0xFFFFFFFFu, a, o));
                m = fmaxf(m, __shfl_xor_sync(0xFFFFFFFFu, m, o));
            }
            if (lane == 0) { s_a = a; s_b = m; }
        }
        __syncthreads();
        pmin = s_a;
        nmax = s_b;

        // ---- pass 2: hard-pair sums (register-resident data) ----
        const float nthr = nmax - 0.45f;   // skipped terms < e^-22.5 * max term
        float psum = 0.0f, nsum = 0.0f;
#pragma unroll
        for (int q = 0; q < 4; q++) {
            const int j0 = (q * 512 + tid) * 4;
            const float s[4] = {sv[q].x, sv[q].y, sv[q].z, sv[q].w};
            const int   l[4] = {lab[q].x, lab[q].y, lab[q].z, lab[q].w};
#pragma unroll
            for (int e = 0; e < 4; e++) {
                const float sj = s[e];
                if (l[e] == li) {
                    if (j0 + e != i && sj - C_MARGIN < nmax)
                        psum += __expf(-C_ALPHA * (sj - C_BASE));
                } else {
                    if (sj + C_MARGIN > pmin && sj > nthr)
                        nsum += __expf(C_BETA * (sj - C_BASE));
                }
            }
        }
#pragma unroll
        for (int o = 16; o; o >>= 1) {
            psum += __shfl_xor_sync(0xFFFFFFFFu, psum, o);
            nsum += __shfl_xor_sync(0xFFFFFFFFu, nsum, o);
        }
        if (lane == 0) { bufC[wid] = psum; bufD[wid] = nsum; }
        __syncthreads();
        if (wid == 0) {
            float ps = bufC[lane & 15];
            float ns = bufD[lane & 15];
#pragma unroll
            for (int o = 8; o; o >>= 1) {
                ps += __shfl_xor_sync(0xFFFFFFFFu, ps, o);
                ns += __shfl_xor_sync(0xFFFFFFFFu, ns, o);
            }
            if (lane == 0) {
                if (pmin < INFINITY && nmax > -INFINITY && ps > 0.0f && ns > 0.0f) {
                    loss_acc += log1pf(ps) / C_ALPHA + log1pf(ns) / C_BETA;
                    cnt_acc++;
                }
            }
        }
        __syncthreads();          // bufA..D consumed before next row's writes
    }

    if (tid == 0) {
        if (cnt_acc > 0) {
            atomicAdd(&g_loss_sum, loss_acc);
            atomicAdd(&g_valid_cnt, cnt_acc);
        }
        __threadfence();
        const unsigned t = atomicAdd(&g_done, 1u);
        if (t == gridDim.x - 1) {
            const int nv = *((volatile int*)&g_valid_cnt);
            const float ls = *((volatile float*)&g_loss_sum);
            out[0] = ls / (float)(nv > 1 ? nv : 1);
        }
    }
}

// ---------------------------------------------------------------------------
extern "C" void kernel_launch(void* const* d_in, const int* in_sizes, int n_in,
                              void* d_out, int out_size) {
    const float* E      = (const float*)d_in[0];
    const int*   labels = (const int*)d_in[1];
    float*       out    = (float*)d_out;

    cudaFuncSetAttribute(gemm_mma_kernel, cudaFuncAttributeMaxDynamicSharedMemorySize,
                         GEMM_SMEM);

    split_kernel<<<NB * ND / 256, 256>>>(E);
    gemm_mma_kernel<<<NTRI, 256, GEMM_SMEM>>>();
    row_kernel<<<NB / RK_ROWS, 512>>>(labels, out);
}

// round 14
// speedup vs baseline: 1.1047x; 1.1047x over previous
#include <cuda_runtime.h>
#include <cuda_bf16.h>
#include <cuda_fp16.h>
#include <cstdint>
#include <math.h>

#define NB 8192
#define ND 128
#define C_ALPHA 2.0f
#define C_BETA 50.0f
#define C_BASE 0.5f
#define C_MARGIN 0.1f

// ---------------------------------------------------------------------------
// Scratch (allocation-free rule: __device__ globals)
// ---------------------------------------------------------------------------
__device__ __half g_simh[(size_t)NB * NB];         // fp16 sim (128 MB)
__device__ __nv_bfloat16 g_Ehi[(size_t)NB * ND];
__device__ __nv_bfloat16 g_Elo[(size_t)NB * ND];
__device__ float g_loss_sum;
__device__ int   g_valid_cnt;
__device__ unsigned g_done;

__device__ __forceinline__ uint32_t smem_u32(const void* p) {
    uint32_t a;
    asm("{ .reg .u64 t; cvta.to.shared.u64 t, %1; cvt.u32.u64 %0, t; }" : "=r"(a) : "l"(p));
    return a;
}

#define LDMATRIX_X4(r0, r1, r2, r3, addr)                                      \
    asm volatile("ldmatrix.sync.aligned.m8n8.x4.shared.b16 {%0,%1,%2,%3}, [%4];" \
                 : "=r"(r0), "=r"(r1), "=r"(r2), "=r"(r3) : "r"(addr))
#define LDMATRIX_X2(r0, r1, addr)                                              \
    asm volatile("ldmatrix.sync.aligned.m8n8.x2.shared.b16 {%0,%1}, [%2];"     \
                 : "=r"(r0), "=r"(r1) : "r"(addr))
#define MMA16816(c, a, b)                                                      \
    asm volatile("mma.sync.aligned.m16n8k16.row.col.f32.bf16.bf16.f32 "        \
                 "{%0,%1,%2,%3}, {%4,%5,%6,%7}, {%8,%9}, {%0,%1,%2,%3};"       \
                 : "+f"((c)[0]), "+f"((c)[1]), "+f"((c)[2]), "+f"((c)[3])      \
                 : "r"((a)[0]), "r"((a)[1]), "r"((a)[2]), "r"((a)[3]),         \
                   "r"((b)[0]), "r"((b)[1]))

__device__ __forceinline__ void tri_decode(int t, int& by, int& bx) {
    int rem = t, y = 0;
    while (rem >= (NB / 128) - y) { rem -= (NB / 128) - y; y++; }
    by = y; bx = y + rem;
}

#define NTILE (NB / 128)
#define NTRI (NTILE * (NTILE + 1) / 2)    // 2080

// ---------------------------------------------------------------------------
// Kernel 0: split fp32 -> bf16 hi/lo, reset scalar accumulators
// ---------------------------------------------------------------------------
__global__ __launch_bounds__(256) void split_kernel(const float* __restrict__ E) {
    int i = blockIdx.x * 256 + threadIdx.x;
    if (i == 0) { g_loss_sum = 0.0f; g_valid_cnt = 0; g_done = 0u; }
    float x = E[i];
    __nv_bfloat16 h = __float2bfloat16(x);
    g_Ehi[i] = h;
    g_Elo[i] = __float2bfloat16(x - __bfloat162float(h));
}

// ---------------------------------------------------------------------------
// Kernel 1: triangular-grid GEMM, fp16 sim output (both triangles)
// ---------------------------------------------------------------------------
#define PAD 8
#define LDT (ND + PAD)                    // 136 bf16 per row
#define ROWB (LDT * 2)                    // 272 B
#define OFF_AHI 0
#define OFF_ALO (OFF_AHI + 128 * ROWB)
#define OFF_BHI (OFF_ALO + 128 * ROWB)
#define OFF_BLO (OFF_BHI + 128 * ROWB)
#define GEMM_SMEM (OFF_BLO + 128 * ROWB)  // 139264
#define TLD 132                           // fp32 transpose-stage stride

__device__ __forceinline__ void gemm_pass(float (&acc)[4][4][4], uint32_t Ab, uint32_t Bb,
                                          int mbase, int nbase, int arow, int acol,
                                          int brow, int bcol) {
#pragma unroll
    for (int k0 = 0; k0 < ND; k0 += 16) {
        uint32_t a[4][4], b[4][2];
#pragma unroll
        for (int mi = 0; mi < 4; mi++) {
            uint32_t ad = Ab + ((mbase + mi * 16 + arow) * LDT + k0 + acol) * 2;
            LDMATRIX_X4(a[mi][0], a[mi][1], a[mi][2], a[mi][3], ad);
        }
#pragma unroll
        for (int ni = 0; ni < 4; ni++) {
            uint32_t bd = Bb + ((nbase + ni * 8 + brow) * LDT + k0 + bcol) * 2;
            LDMATRIX_X2(b[ni][0], b[ni][1], bd);
        }
#pragma unroll
        for (int mi = 0; mi < 4; mi++)
#pragma unroll
            for (int ni = 0; ni < 4; ni++)
                MMA16816(acc[mi][ni], a[mi], b[ni]);
    }
}

__global__ __launch_bounds__(256, 1) void gemm_mma_kernel() {
    int by, bx;
    tri_decode(blockIdx.x, by, bx);

    extern __shared__ char smem[];
    const uint32_t sbase = smem_u32(smem);
    const int tid  = threadIdx.x;
    const int wid  = tid >> 5;
    const int lane = tid & 31;
    const int bm = by * 128;
    const int bn = bx * 128;
    const bool diag = (bx == by);

    // ---- plain uint4 tile loads ----
    for (int t = tid; t < 2048; t += 256) {
        const int r = t >> 4;
        const int c = t & 15;
        const uint32_t so = (uint32_t)r * ROWB + c * 16;
        const size_t ga = (size_t)(bm + r) * ND + c * 8;
        *(uint4*)(smem + OFF_AHI + so) = *(const uint4*)(g_Ehi + ga);
        *(uint4*)(smem + OFF_ALO + so) = *(const uint4*)(g_Elo + ga);
        if (!diag) {
            const size_t gb = (size_t)(bn + r) * ND + c * 8;
            *(uint4*)(smem + OFF_BHI + so) = *(const uint4*)(g_Ehi + gb);
            *(uint4*)(smem + OFF_BLO + so) = *(const uint4*)(g_Elo + gb);
        }
    }
    __syncthreads();

    const int warp_m = wid >> 2;
    const int warp_n = wid & 3;
    const int mbase = warp_m * 64;
    const int nbase = warp_n * 32;
    const int arow = ((lane >> 3) & 1) * 8 + (lane & 7);
    const int acol = ((lane >> 4) & 1) * 8;
    const int brow = lane & 7;
    const int bcol = ((lane >> 3) & 1) * 8;

    float acc[4][4][4];
#pragma unroll
    for (int mi = 0; mi < 4; mi++)
#pragma unroll
        for (int ni = 0; ni < 4; ni++)
#pragma unroll
            for (int q = 0; q < 4; q++) acc[mi][ni][q] = 0.0f;

    const uint32_t aHi = sbase + OFF_AHI;
    const uint32_t aLo = sbase + OFF_ALO;
    const uint32_t bHi = diag ? aHi : sbase + OFF_BHI;
    const uint32_t bLo = diag ? aLo : sbase + OFF_BLO;

    gemm_pass(acc, aHi, bHi, mbase, nbase, arow, acol, brow, bcol);   // hi*hi
    gemm_pass(acc, aHi, bLo, mbase, nbase, arow, acol, brow, bcol);   // hi*lo
    gemm_pass(acc, aLo, bHi, mbase, nbase, arow, acol, brow, bcol);   // lo*hi

    // ---- direct store (fp16, half2 per lane) ----
    const int g   = lane >> 2;
    const int tig = lane & 3;
#pragma unroll
    for (int mi = 0; mi < 4; mi++) {
        const size_t row0 = (size_t)(bm + mbase + mi * 16 + g);
        const size_t row1 = row0 + 8;
#pragma unroll
        for (int ni = 0; ni < 4; ni++) {
            const int col = bn + nbase + ni * 8 + tig * 2;
            __half2 h0 = __floats2half2_rn(acc[mi][ni][0], acc[mi][ni][1]);
            __half2 h1 = __floats2half2_rn(acc[mi][ni][2], acc[mi][ni][3]);
            *(__half2*)(g_simh + row0 * NB + col) = h0;
            *(__half2*)(g_simh + row1 * NB + col) = h1;
        }
    }

    // ---- transposed store for off-diagonal tiles (fp32 SMEM stage -> fp16) ----
    if (!diag) {
        __syncthreads();               // operand reads done; reuse smem
        float* st = (float*)smem;      // [128][TLD]
#pragma unroll
        for (int mi = 0; mi < 4; mi++) {
            const int r0 = mbase + mi * 16 + g;
#pragma unroll
            for (int ni = 0; ni < 4; ni++) {
                const int c0 = nbase + ni * 8 + tig * 2;
                st[(c0 + 0) * TLD + r0]     = acc[mi][ni][0];
                st[(c0 + 1) * TLD + r0]     = acc[mi][ni][1];
                st[(c0 + 0) * TLD + r0 + 8] = acc[mi][ni][2];
                st[(c0 + 1) * TLD + r0 + 8] = acc[mi][ni][3];
            }
        }
        __syncthreads();
        for (int t = tid; t < 128 * 32; t += 256) {
            const int r  = t >> 5;
            const int c4 = (t & 31) * 4;
            float4 v = *(float4*)(st + r * TLD + c4);
            __half2 h0 = __floats2half2_rn(v.x, v.y);
            __half2 h1 = __floats2half2_rn(v.z, v.w);
            uint2 pk = make_uint2(*(uint32_t*)&h0, *(uint32_t*)&h1);
            *(uint2*)(g_simh + (size_t)(bn + r) * NB + bm + c4) = pk;
        }
    }
}

// ---------------------------------------------------------------------------
// Kernel 2: per-row mining + loss. 512 threads, 8 rows/CTA; fp16 row data
// (2 uint4 = 16 halves/thread), labels in registers; warp-shuffle reduces;
// per-CTA loss accumulation; last-CTA finalize.
// validity: anyPos<=>pmin<inf, anyNeg<=>nmax>-inf, hardPos<=>psum>0,
// hardNeg<=>nsum>0 (nmax elem is hard & above cutoff whenever any is).
// ---------------------------------------------------------------------------
#define RK_ROWS 8

__global__ __launch_bounds__(512, 2) void row_kernel(const int* __restrict__ labels,
                                                     float* __restrict__ out) {
    __shared__ float bufA[16], bufB[16];   // pass-1 (extrema)
    __shared__ float bufC[16], bufD[16];   // pass-2 (sums)
    __shared__ float s_a, s_b;

    const int tid  = threadIdx.x;
    const int lane = tid & 31;
    const int wid  = tid >> 5;
    const int i0   = blockIdx.x * RK_ROWS;

    // labels for the 16 elements this thread owns: [8*tid..8*tid+7] and
    // [4096+8*tid..4096+8*tid+7]  (int4 pairs)
    int4 lab[4];
#pragma unroll
    for (int q = 0; q < 2; q++) {
        lab[2 * q + 0] = ((const int4*)labels)[(q * 512 + tid) * 2 + 0];
        lab[2 * q + 1] = ((const int4*)labels)[(q * 512 + tid) * 2 + 1];
    }

    float loss_acc = 0.0f;
    int   cnt_acc  = 0;

    for (int r = 0; r < RK_ROWS; r++) {
        const int i  = i0 + r;
        const int li = __ldg(labels + i);

        // 16 halves per thread (2 x uint4)
        uint4 hv[2];
        const uint4* hrow = (const uint4*)(g_simh + (size_t)i * NB);
#pragma unroll
        for (int q = 0; q < 2; q++) hv[q] = hrow[q * 512 + tid];

        // unpack to floats
        float s[16];
        int   l[16];
#pragma unroll
        for (int q = 0; q < 2; q++) {
            const uint32_t w[4] = {hv[q].x, hv[q].y, hv[q].z, hv[q].w};
#pragma unroll
            for (int p = 0; p < 4; p++) {
                float2 f = __half22float2(*(const __half2*)&w[p]);
                s[q * 8 + p * 2 + 0] = f.x;
                s[q * 8 + p * 2 + 1] = f.y;
            }
            l[q * 8 + 0] = lab[2 * q].x;     l[q * 8 + 1] = lab[2 * q].y;
            l[q * 8 + 2] = lab[2 * q].z;     l[q * 8 + 3] = lab[2 * q].w;
            l[q * 8 + 4] = lab[2 * q + 1].x; l[q * 8 + 5] = lab[2 * q + 1].y;
            l[q * 8 + 6] = lab[2 * q + 1].z; l[q * 8 + 7] = lab[2 * q + 1].w;
        }

        // ---- pass 1: extrema ----
        float pmin = INFINITY, nmax = -INFINITY;
#pragma unroll
        for (int q = 0; q < 2; q++) {
            const int j0 = (q * 512 + tid) * 8;
#pragma unroll
            for (int e = 0; e < 8; e++) {
                const float sj = s[q * 8 + e];
                if (l[q * 8 + e] == li) { if (j0 + e != i) pmin = fminf(pmin, sj); }
                else nmax = fmaxf(nmax, sj);
            }
        }
#pragma unroll
        for (int o = 16; o; o >>= 1) {
            pmin = fminf(pmin, __shfl_xor_sync(0xFFFFFFFFu, pmin, o));
            nmax = fmaxf(nmax, __shfl_xor_sync(0xFFFFFFFFu, nmax, o));
        }
        if (lane == 0) { bufA[wid] = pmin; bufB[wid] = nmax; }
        __syncthreads();
        if (wid == 0) {
            float a = bufA[lane & 15];
            float m = bufB[lane & 15];
#pragma unroll
            for (int o = 8; o; o >>= 1) {
                a = fminf(a, __shfl_xor_sync(0xFFFFFFFFu, a, o));
                m = fmaxf(m, __shfl_xor_sync(0xFFFFFFFFu, m, o));
            }
            if (lane == 0) { s_a = a; s_b = m; }
        }
        __syncthreads();
        pmin = s_a;
        nmax = s_b;

        // ---- pass 2: hard-pair sums ----
        const float nthr = nmax - 0.45f;   // skipped terms < e^-22.5 * max term
        float psum = 0.0f, nsum = 0.0f;
#pragma unroll
        for (int q = 0; q < 2; q++) {
            const int j0 = (q * 512 + tid) * 8;
#pragma unroll
            for (int e = 0; e < 8; e++) {
                const float sj = s[q * 8 + e];
                if (l[q * 8 + e] == li) {
                    if (j0 + e != i && sj - C_MARGIN < nmax)
                        psum += __expf(-C_ALPHA * (sj - C_BASE));
                } else {
                    if (sj + C_MARGIN > pmin && sj > nthr)
                        nsum += __expf(C_BETA * (sj - C_BASE));
                }
            }
        }
#pragma unroll
        for (int o = 16; o; o >>= 1) {
            psum += __shfl_xor_sync(0xFFFFFFFFu, psum, o);
            nsum += __shfl_xor_sync(0xFFFFFFFFu, nsum, o);
        }
        if (lane == 0) { bufC[wid] = psum; bufD[wid] = nsum; }
        __syncthreads();
        if (wid == 0) {
            float ps = bufC[lane & 15];
            float ns = bufD[lane & 15];
#pragma unroll
            for (int o = 8; o; o >>= 1) {
                ps += __shfl_xor_sync(0xFFFFFFFFu, ps, o);
                ns += __shfl_xor_sync(0xFFFFFFFFu, ns, o);
            }
            if (lane == 0) {
                if (pmin < INFINITY && nmax > -INFINITY && ps > 0.0f && ns > 0.0f) {
                    loss_acc += log1pf(ps) / C_ALPHA + log1pf(ns) / C_BETA;
                    cnt_acc++;
                }
            }
        }
        __syncthreads();          // bufs consumed before next row's writes
    }

    if (tid == 0) {
        if (cnt_acc > 0) {
            atomicAdd(&g_loss_sum, loss_acc);
            atomicAdd(&g_valid_cnt, cnt_acc);
        }
        __threadfence();
        const unsigned t = atomicAdd(&g_done, 1u);
        if (t == gridDim.x - 1) {
            const int nv = *((volatile int*)&g_valid_cnt);
            const float ls = *((volatile float*)&g_loss_sum);
            out[0] = ls / (float)(nv > 1 ? nv : 1);
        }
    }
}

// ---------------------------------------------------------------------------
extern "C" void kernel_launch(void* const* d_in, const int* in_sizes, int n_in,
                              void* d_out, int out_size) {
    const float* E      = (const float*)d_in[0];
    const int*   labels = (const int*)d_in[1];
    float*       out    = (float*)d_out;

    cudaFuncSetAttribute(gemm_mma_kernel, cudaFuncAttributeMaxDynamicSharedMemorySize,
                         GEMM_SMEM);

    split_kernel<<<NB * ND / 256, 256>>>(E);
    gemm_mma_kernel<<<NTRI, 256, GEMM_SMEM>>>();
    row_kernel<<<NB / RK_ROWS, 512>>>(labels, out);
}

// round 15
// speedup vs baseline: 1.4730x; 1.3333x over previous
#include <cuda_runtime.h>
#include <cuda_fp16.h>
#include <cstdint>
#include <math.h>

#define NB 8192
#define ND 128
#define C_ALPHA 2.0f
#define C_BETA 50.0f
#define C_BASE 0.5f
#define C_MARGIN 0.1f

// ---------------------------------------------------------------------------
// Scratch (allocation-free rule: __device__ globals)
// ---------------------------------------------------------------------------
__device__ __half g_simh[(size_t)NB * NB];         // fp16 sim (128 MB)
__device__ __half g_Eh[(size_t)NB * ND];           // fp16 embeddings (2 MB)
__device__ float g_loss_sum;
__device__ int   g_valid_cnt;
__device__ unsigned g_done;

__device__ __forceinline__ uint32_t smem_u32(const void* p) {
    uint32_t a;
    asm("{ .reg .u64 t; cvta.to.shared.u64 t, %1; cvt.u32.u64 %0, t; }" : "=r"(a) : "l"(p));
    return a;
}

#define LDMATRIX_X4(r0, r1, r2, r3, addr)                                      \
    asm volatile("ldmatrix.sync.aligned.m8n8.x4.shared.b16 {%0,%1,%2,%3}, [%4];" \
                 : "=r"(r0), "=r"(r1), "=r"(r2), "=r"(r3) : "r"(addr))
#define LDMATRIX_X2(r0, r1, addr)                                              \
    asm volatile("ldmatrix.sync.aligned.m8n8.x2.shared.b16 {%0,%1}, [%2];"     \
                 : "=r"(r0), "=r"(r1) : "r"(addr))
#define MMA16816F(c, a, b)                                                     \
    asm volatile("mma.sync.aligned.m16n8k16.row.col.f32.f16.f16.f32 "          \
                 "{%0,%1,%2,%3}, {%4,%5,%6,%7}, {%8,%9}, {%0,%1,%2,%3};"       \
                 : "+f"((c)[0]), "+f"((c)[1]), "+f"((c)[2]), "+f"((c)[3])      \
                 : "r"((a)[0]), "r"((a)[1]), "r"((a)[2]), "r"((a)[3]),         \
                   "r"((b)[0]), "r"((b)[1]))

__device__ __forceinline__ void tri_decode(int t, int& by, int& bx) {
    int rem = t, y = 0;
    while (rem >= (NB / 128) - y) { rem -= (NB / 128) - y; y++; }
    by = y; bx = y + rem;
}

#define NTILE (NB / 128)
#define NTRI (NTILE * (NTILE + 1) / 2)    // 2080

// ---------------------------------------------------------------------------
// Kernel 0: E fp32 -> fp16, reset scalar accumulators
// ---------------------------------------------------------------------------
__global__ __launch_bounds__(256) void split_kernel(const float* __restrict__ E) {
    int i = blockIdx.x * 256 + threadIdx.x;
    if (i == 0) { g_loss_sum = 0.0f; g_valid_cnt = 0; g_done = 0u; }
    g_Eh[i] = __float2half_rn(E[i]);
}

// ---------------------------------------------------------------------------
// Kernel 1: single-pass fp16 GEMM, triangular grid, 2 CTAs/SM (70 KB SMEM),
// fp16 sim output to both triangles.
// ---------------------------------------------------------------------------
#define PAD 8
#define LDT (ND + PAD)                    // 136 fp16 per row
#define ROWB (LDT * 2)                    // 272 B
#define OFF_A 0
#define OFF_B (OFF_A + 128 * ROWB)        // 34816
#define GEMM_SMEM (OFF_B + 128 * ROWB)    // 69632
#define TLD 132                           // fp32 transpose-stage stride (67584 <= 69632)

__global__ __launch_bounds__(256, 2) void gemm_mma_kernel() {
    int by, bx;
    tri_decode(blockIdx.x, by, bx);

    extern __shared__ char smem[];
    const uint32_t sbase = smem_u32(smem);
    const int tid  = threadIdx.x;
    const int wid  = tid >> 5;
    const int lane = tid & 31;
    const int bm = by * 128;
    const int bn = bx * 128;
    const bool diag = (bx == by);

    // ---- tile loads (uint4) ----
    for (int t = tid; t < 2048; t += 256) {
        const int r = t >> 4;
        const int c = t & 15;
        const uint32_t so = (uint32_t)r * ROWB + c * 16;
        *(uint4*)(smem + OFF_A + so) = *(const uint4*)(g_Eh + (size_t)(bm + r) * ND + c * 8);
        if (!diag)
            *(uint4*)(smem + OFF_B + so) = *(const uint4*)(g_Eh + (size_t)(bn + r) * ND + c * 8);
    }
    __syncthreads();

    const int warp_m = wid >> 2;
    const int warp_n = wid & 3;
    const int mbase = warp_m * 64;
    const int nbase = warp_n * 32;
    const int arow = ((lane >> 3) & 1) * 8 + (lane & 7);
    const int acol = ((lane >> 4) & 1) * 8;
    const int brow = lane & 7;
    const int bcol = ((lane >> 3) & 1) * 8;

    float acc[4][4][4];
#pragma unroll
    for (int mi = 0; mi < 4; mi++)
#pragma unroll
        for (int ni = 0; ni < 4; ni++)
#pragma unroll
            for (int q = 0; q < 4; q++) acc[mi][ni][q] = 0.0f;

    const uint32_t Ab = sbase + OFF_A;
    const uint32_t Bb = diag ? Ab : sbase + OFF_B;

#pragma unroll
    for (int k0 = 0; k0 < ND; k0 += 16) {
        uint32_t a[4][4], b[4][2];
#pragma unroll
        for (int mi = 0; mi < 4; mi++) {
            uint32_t ad = Ab + ((mbase + mi * 16 + arow) * LDT + k0 + acol) * 2;
            LDMATRIX_X4(a[mi][0], a[mi][1], a[mi][2], a[mi][3], ad);
        }
#pragma unroll
        for (int ni = 0; ni < 4; ni++) {
            uint32_t bd = Bb + ((nbase + ni * 8 + brow) * LDT + k0 + bcol) * 2;
            LDMATRIX_X2(b[ni][0], b[ni][1], bd);
        }
#pragma unroll
        for (int mi = 0; mi < 4; mi++)
#pragma unroll
            for (int ni = 0; ni < 4; ni++)
                MMA16816F(acc[mi][ni], a[mi], b[ni]);
    }

    // ---- direct store (fp16, half2 per lane) ----
    const int g   = lane >> 2;
    const int tig = lane & 3;
#pragma unroll
    for (int mi = 0; mi < 4; mi++) {
        const size_t row0 = (size_t)(bm + mbase + mi * 16 + g);
        const size_t row1 = row0 + 8;
#pragma unroll
        for (int ni = 0; ni < 4; ni++) {
            const int col = bn + nbase + ni * 8 + tig * 2;
            __half2 h0 = __floats2half2_rn(acc[mi][ni][0], acc[mi][ni][1]);
            __half2 h1 = __floats2half2_rn(acc[mi][ni][2], acc[mi][ni][3]);
            *(__half2*)(g_simh + row0 * NB + col) = h0;
            *(__half2*)(g_simh + row1 * NB + col) = h1;
        }
    }

    // ---- transposed store for off-diagonal tiles (fp32 SMEM stage -> fp16) ----
    if (!diag) {
        __syncthreads();               // operand reads done; reuse smem
        float* st = (float*)smem;      // [128][TLD]
#pragma unroll
        for (int mi = 0; mi < 4; mi++) {
            const int r0 = mbase + mi * 16 + g;
#pragma unroll
            for (int ni = 0; ni < 4; ni++) {
                const int c0 = nbase + ni * 8 + tig * 2;
                st[(c0 + 0) * TLD + r0]     = acc[mi][ni][0];
                st[(c0 + 1) * TLD + r0]     = acc[mi][ni][1];
                st[(c0 + 0) * TLD + r0 + 8] = acc[mi][ni][2];
                st[(c0 + 1) * TLD + r0 + 8] = acc[mi][ni][3];
            }
        }
        __syncthreads();
        for (int t = tid; t < 128 * 32; t += 256) {
            const int r  = t >> 5;
            const int c4 = (t & 31) * 4;
            float4 v = *(float4*)(st + r * TLD + c4);
            __half2 h0 = __floats2half2_rn(v.x, v.y);
            __half2 h1 = __floats2half2_rn(v.z, v.w);
            uint2 pk = make_uint2(*(uint32_t*)&h0, *(uint32_t*)&h1);
            *(uint2*)(g_simh + (size_t)(bn + r) * NB + bm + c4) = pk;
        }
    }
}

// ---------------------------------------------------------------------------
// Kernel 2: per-row mining + loss (unchanged from round 14). 512 threads,
// 8 rows/CTA; fp16 row data, labels in registers; warp-shuffle reduces;
// per-CTA loss accumulation; last-CTA finalize.
// validity: anyPos<=>pmin<inf, anyNeg<=>nmax>-inf, hardPos<=>psum>0,
// hardNeg<=>nsum>0 (nmax elem is hard & above cutoff whenever any is).
// ---------------------------------------------------------------------------
#define RK_ROWS 8

__global__ __launch_bounds__(512, 2) void row_kernel(const int* __restrict__ labels,
                                                     float* __restrict__ out) {
    __shared__ float bufA[16], bufB[16];   // pass-1 (extrema)
    __shared__ float bufC[16], bufD[16];   // pass-2 (sums)
    __shared__ float s_a, s_b;

    const int tid  = threadIdx.x;
    const int lane = tid & 31;
    const int wid  = tid >> 5;
    const int i0   = blockIdx.x * RK_ROWS;

    int4 lab[4];
#pragma unroll
    for (int q = 0; q < 2; q++) {
        lab[2 * q + 0] = ((const int4*)labels)[(q * 512 + tid) * 2 + 0];
        lab[2 * q + 1] = ((const int4*)labels)[(q * 512 + tid) * 2 + 1];
    }

    float loss_acc = 0.0f;
    int   cnt_acc  = 0;

    for (int r = 0; r < RK_ROWS; r++) {
        const int i  = i0 + r;
        const int li = __ldg(labels + i);

        uint4 hv[2];
        const uint4* hrow = (const uint4*)(g_simh + (size_t)i * NB);
#pragma unroll
        for (int q = 0; q < 2; q++) hv[q] = hrow[q * 512 + tid];

        float s[16];
        int   l[16];
#pragma unroll
        for (int q = 0; q < 2; q++) {
            const uint32_t w[4] = {hv[q].x, hv[q].y, hv[q].z, hv[q].w};
#pragma unroll
            for (int p = 0; p < 4; p++) {
                float2 f = __half22float2(*(const __half2*)&w[p]);
                s[q * 8 + p * 2 + 0] = f.x;
                s[q * 8 + p * 2 + 1] = f.y;
            }
            l[q * 8 + 0] = lab[2 * q].x;     l[q * 8 + 1] = lab[2 * q].y;
            l[q * 8 + 2] = lab[2 * q].z;     l[q * 8 + 3] = lab[2 * q].w;
            l[q * 8 + 4] = lab[2 * q + 1].x; l[q * 8 + 5] = lab[2 * q + 1].y;
            l[q * 8 + 6] = lab[2 * q + 1].z; l[q * 8 + 7] = lab[2 * q + 1].w;
        }

        // ---- pass 1: extrema ----
        float pmin = INFINITY, nmax = -INFINITY;
#pragma unroll
        for (int q = 0; q < 2; q++) {
            const int j0 = (q * 512 + tid) * 8;
#pragma unroll
            for (int e = 0; e < 8; e++) {
                const float sj = s[q * 8 + e];
                if (l[q * 8 + e] == li) { if (j0 + e != i) pmin = fminf(pmin, sj); }
                else nmax = fmaxf(nmax, sj);
            }
        }
#pragma unroll
        for (int o = 16; o; o >>= 1) {
            pmin = fminf(pmin, __shfl_xor_sync(0xFFFFFFFFu, pmin, o));
            nmax = fmaxf(nmax, __shfl_xor_sync(0xFFFFFFFFu, nmax, o));
        }
        if (lane == 0) { bufA[wid] = pmin; bufB[wid] = nmax; }
        __syncthreads();
        if (wid == 0) {
            float a = bufA[lane & 15];
            float m = bufB[lane & 15];
#pragma unroll
            for (int o = 8; o; o >>= 1) {
                a = fminf(a, __shfl_xor_sync(0xFFFFFFFFu, a, o));
                m = fmaxf(m, __shfl_xor_sync(0xFFFFFFFFu, m, o));
            }
            if (lane == 0) { s_a = a; s_b = m; }
        }
        __syncthreads();
        pmin = s_a;
        nmax = s_b;

        // ---- pass 2: hard-pair sums ----
        const float nthr = nmax - 0.45f;   // skipped terms < e^-22.5 * max term
        float psum = 0.0f, nsum = 0.0f;
#pragma unroll
        for (int q = 0; q < 2; q++) {
            const int j0 = (q * 512 + tid) * 8;
#pragma unroll
            for (int e = 0; e < 8; e++) {
                const float sj = s[q * 8 + e];
                if (l[q * 8 + e] == li) {
                    if (j0 + e != i && sj - C_MARGIN < nmax)
                        psum += __expf(-C_ALPHA * (sj - C_BASE));
                } else {
                    if (sj + C_MARGIN > pmin && sj > nthr)
                        nsum += __expf(C_BETA * (sj - C_BASE));
                }
            }
        }
#pragma unroll
        for (int o = 16; o; o >>= 1) {
            psum += __shfl_xor_sync(0xFFFFFFFFu, psum, o);
            nsum += __shfl_xor_sync(0xFFFFFFFFu, nsum, o);
        }
        if (lane == 0) { bufC[wid] = psum; bufD[wid] = nsum; }
        __syncthreads();
        if (wid == 0) {
            float ps = bufC[lane & 15];
            float ns = bufD[lane & 15];
#pragma unroll
            for (int o = 8; o; o >>= 1) {
                ps += __shfl_xor_sync(0xFFFFFFFFu, ps, o);
                ns += __shfl_xor_sync(0xFFFFFFFFu, ns, o);
            }
            if (lane == 0) {
                if (pmin < INFINITY && nmax > -INFINITY && ps > 0.0f && ns > 0.0f) {
                    loss_acc += log1pf(ps) / C_ALPHA + log1pf(ns) / C_BETA;
                    cnt_acc++;
                }
            }
        }
        __syncthreads();          // bufs consumed before next row's writes
    }

    if (tid == 0) {
        if (cnt_acc > 0) {
            atomicAdd(&g_loss_sum, loss_acc);
            atomicAdd(&g_valid_cnt, cnt_acc);
        }
        __threadfence();
        const unsigned t = atomicAdd(&g_done, 1u);
        if (t == gridDim.x - 1) {
            const int nv = *((volatile int*)&g_valid_cnt);
            const float ls = *((volatile float*)&g_loss_sum);
            out[0] = ls / (float)(nv > 1 ? nv : 1);
        }
    }
}

// ---------------------------------------------------------------------------
extern "C" void kernel_launch(void* const* d_in, const int* in_sizes, int n_in,
                              void* d_out, int out_size) {
    const float* E      = (const float*)d_in[0];
    const int*   labels = (const int*)d_in[1];
    float*       out    = (float*)d_out;

    cudaFuncSetAttribute(gemm_mma_kernel, cudaFuncAttributeMaxDynamicSharedMemorySize,
                         GEMM_SMEM);

    split_kernel<<<NB * ND / 256, 256>>>(E);
    gemm_mma_kernel<<<NTRI, 256, GEMM_SMEM>>>();
    row_kernel<<<NB / RK_ROWS, 512>>>(labels, out);
}

// round 16
// speedup vs baseline: 2.0508x; 1.3923x over previous
#include <cuda_runtime.h>
#include <cuda_fp16.h>
#include <cstdint>
#include <math.h>

#define NB 8192
#define ND 128
#define NCLS 512
#define CLS_CAP 64
#define C_ALPHA 2.0f
#define C_BETA 50.0f
#define C_BASE 0.5f
#define C_MARGIN 0.1f

// ---------------------------------------------------------------------------
// Scratch (allocation-free rule: __device__ globals)
// ---------------------------------------------------------------------------
__device__ __half g_simh[(size_t)NB * NB];         // fp16 sim (128 MB)
__device__ __half g_Eh[(size_t)NB * ND];           // fp16 embeddings
__device__ int   g_cls_cnt[NCLS];
__device__ int   g_cls_mem[NCLS * CLS_CAP];
__device__ float g_pos[(size_t)NB * CLS_CAP];      // gathered same-class sims (2 MB)
__device__ float g_loss_sum;
__device__ int   g_valid_cnt;
__device__ unsigned g_done;

__device__ __forceinline__ uint32_t smem_u32(const void* p) {
    uint32_t a;
    asm("{ .reg .u64 t; cvta.to.shared.u64 t, %1; cvt.u32.u64 %0, t; }" : "=r"(a) : "l"(p));
    return a;
}

#define LDMATRIX_X4(r0, r1, r2, r3, addr)                                      \
    asm volatile("ldmatrix.sync.aligned.m8n8.x4.shared.b16 {%0,%1,%2,%3}, [%4];" \
                 : "=r"(r0), "=r"(r1), "=r"(r2), "=r"(r3) : "r"(addr))
#define LDMATRIX_X2(r0, r1, addr)                                              \
    asm volatile("ldmatrix.sync.aligned.m8n8.x2.shared.b16 {%0,%1}, [%2];"     \
                 : "=r"(r0), "=r"(r1) : "r"(addr))
#define MMA16816F(c, a, b)                                                     \
    asm volatile("mma.sync.aligned.m16n8k16.row.col.f32.f16.f16.f32 "          \
                 "{%0,%1,%2,%3}, {%4,%5,%6,%7}, {%8,%9}, {%0,%1,%2,%3};"       \
                 : "+f"((c)[0]), "+f"((c)[1]), "+f"((c)[2]), "+f"((c)[3])      \
                 : "r"((a)[0]), "r"((a)[1]), "r"((a)[2]), "r"((a)[3]),         \
                   "r"((b)[0]), "r"((b)[1]))

__device__ __forceinline__ void tri_decode(int t, int& by, int& bx) {
    int rem = t, y = 0;
    while (rem >= (NB / 128) - y) { rem -= (NB / 128) - y; y++; }
    by = y; bx = y + rem;
}

#define NTILE (NB / 128)
#define NTRI (NTILE * (NTILE + 1) / 2)    // 2080

// ---------------------------------------------------------------------------
// Kernel 0: E fp32 -> fp16; zero class counters; reset scalars
// ---------------------------------------------------------------------------
__global__ __launch_bounds__(256) void split_kernel(const float* __restrict__ E) {
    int i = blockIdx.x * 256 + threadIdx.x;
    if (i == 0) { g_loss_sum = 0.0f; g_valid_cnt = 0; g_done = 0u; }
    if (i < NCLS) g_cls_cnt[i] = 0;
    g_Eh[i] = __float2half_rn(E[i]);
}

// ---------------------------------------------------------------------------
// Kernel 1: single-pass fp16 GEMM, triangular grid, 2 CTAs/SM (unchanged R15)
// ---------------------------------------------------------------------------
#define PAD 8
#define LDT (ND + PAD)
#define ROWB (LDT * 2)
#define OFF_A 0
#define OFF_B (OFF_A + 128 * ROWB)
#define GEMM_SMEM (OFF_B + 128 * ROWB)    // 69632
#define TLD 132

__global__ __launch_bounds__(256, 2) void gemm_mma_kernel() {
    int by, bx;
    tri_decode(blockIdx.x, by, bx);

    extern __shared__ char smem[];
    const uint32_t sbase = smem_u32(smem);
    const int tid  = threadIdx.x;
    const int wid  = tid >> 5;
    const int lane = tid & 31;
    const int bm = by * 128;
    const int bn = bx * 128;
    const bool diag = (bx == by);

    for (int t = tid; t < 2048; t += 256) {
        const int r = t >> 4;
        const int c = t & 15;
        const uint32_t so = (uint32_t)r * ROWB + c * 16;
        *(uint4*)(smem + OFF_A + so) = *(const uint4*)(g_Eh + (size_t)(bm + r) * ND + c * 8);
        if (!diag)
            *(uint4*)(smem + OFF_B + so) = *(const uint4*)(g_Eh + (size_t)(bn + r) * ND + c * 8);
    }
    __syncthreads();

    const int warp_m = wid >> 2;
    const int warp_n = wid & 3;
    const int mbase = warp_m * 64;
    const int nbase = warp_n * 32;
    const int arow = ((lane >> 3) & 1) * 8 + (lane & 7);
    const int acol = ((lane >> 4) & 1) * 8;
    const int brow = lane & 7;
    const int bcol = ((lane >> 3) & 1) * 8;

    float acc[4][4][4];
#pragma unroll
    for (int mi = 0; mi < 4; mi++)
#pragma unroll
        for (int ni = 0; ni < 4; ni++)
#pragma unroll
            for (int q = 0; q < 4; q++) acc[mi][ni][q] = 0.0f;

    const uint32_t Ab = sbase + OFF_A;
    const uint32_t Bb = diag ? Ab : sbase + OFF_B;

#pragma unroll
    for (int k0 = 0; k0 < ND; k0 += 16) {
        uint32_t a[4][4], b[4][2];
#pragma unroll
        for (int mi = 0; mi < 4; mi++) {
            uint32_t ad = Ab + ((mbase + mi * 16 + arow) * LDT + k0 + acol) * 2;
            LDMATRIX_X4(a[mi][0], a[mi][1], a[mi][2], a[mi][3], ad);
        }
#pragma unroll
        for (int ni = 0; ni < 4; ni++) {
            uint32_t bd = Bb + ((nbase + ni * 8 + brow) * LDT + k0 + bcol) * 2;
            LDMATRIX_X2(b[ni][0], b[ni][1], bd);
        }
#pragma unroll
        for (int mi = 0; mi < 4; mi++)
#pragma unroll
            for (int ni = 0; ni < 4; ni++)
                MMA16816F(acc[mi][ni], a[mi], b[ni]);
    }

    const int g   = lane >> 2;
    const int tig = lane & 3;
#pragma unroll
    for (int mi = 0; mi < 4; mi++) {
        const size_t row0 = (size_t)(bm + mbase + mi * 16 + g);
        const size_t row1 = row0 + 8;
#pragma unroll
        for (int ni = 0; ni < 4; ni++) {
            const int col = bn + nbase + ni * 8 + tig * 2;
            __half2 h0 = __floats2half2_rn(acc[mi][ni][0], acc[mi][ni][1]);
            __half2 h1 = __floats2half2_rn(acc[mi][ni][2], acc[mi][ni][3]);
            *(__half2*)(g_simh + row0 * NB + col) = h0;
            *(__half2*)(g_simh + row1 * NB + col) = h1;
        }
    }

    if (!diag) {
        __syncthreads();
        float* st = (float*)smem;
#pragma unroll
        for (int mi = 0; mi < 4; mi++) {
            const int r0 = mbase + mi * 16 + g;
#pragma unroll
            for (int ni = 0; ni < 4; ni++) {
                const int c0 = nbase + ni * 8 + tig * 2;
                st[(c0 + 0) * TLD + r0]     = acc[mi][ni][0];
                st[(c0 + 1) * TLD + r0]     = acc[mi][ni][1];
                st[(c0 + 0) * TLD + r0 + 8] = acc[mi][ni][2];
                st[(c0 + 1) * TLD + r0 + 8] = acc[mi][ni][3];
            }
        }
        __syncthreads();
        for (int t = tid; t < 128 * 32; t += 256) {
            const int r  = t >> 5;
            const int c4 = (t & 31) * 4;
            float4 v = *(float4*)(st + r * TLD + c4);
            __half2 h0 = __floats2half2_rn(v.x, v.y);
            __half2 h1 = __floats2half2_rn(v.z, v.w);
            uint2 pk = make_uint2(*(uint32_t*)&h0, *(uint32_t*)&h1);
            *(uint2*)(g_simh + (size_t)(bn + r) * NB + bm + c4) = pk;
        }
    }
}

// ---------------------------------------------------------------------------
// Kernel 2: build per-class member lists
// ---------------------------------------------------------------------------
__global__ __launch_bounds__(256) void class_build_kernel(const int* __restrict__ labels) {
    int i = blockIdx.x * 256 + threadIdx.x;
    int c = labels[i];
    int s = atomicAdd(&g_cls_cnt[c], 1);
    if (s < CLS_CAP) g_cls_mem[c * CLS_CAP + s] = i;
}

// ---------------------------------------------------------------------------
// Kernel 3: gather same-class sims into g_pos, poison them in g_simh (-1000).
// One warp per row; slots 0..63 handled by lane and lane+32.
// ---------------------------------------------------------------------------
__global__ __launch_bounds__(256) void gather_poison_kernel(const int* __restrict__ labels) {
    const int wid  = threadIdx.x >> 5;
    const int lane = threadIdx.x & 31;
    const int i    = blockIdx.x * 8 + wid;
    const int li   = labels[i];
    const int cnt  = min(g_cls_cnt[li], CLS_CAP);
    const __half poison = __float2half_rn(-1000.0f);

#pragma unroll
    for (int h = 0; h < 2; h++) {
        const int slot = lane + h * 32;
        int idx = (slot < cnt) ? g_cls_mem[li * CLS_CAP + slot] : -1;
        float s = INFINITY;
        if (idx >= 0 && idx != i) s = __half2float(g_simh[(size_t)i * NB + idx]);
        g_pos[(size_t)i * CLS_CAP + slot] = s;
        if (idx >= 0) g_simh[(size_t)i * NB + idx] = poison;   // incl. self
    }
}

// ---------------------------------------------------------------------------
// Kernel 4: label-free per-row mining. 512 threads, 8 rows/CTA.
// pass1: row max via packed hmax2 (negatives only; poisons never win).
//        warp0 also computes pmin over gathered positives.
// pass2: nsum with single fused threshold tcut; warp0 adds psum.
// ---------------------------------------------------------------------------
#define RK_ROWS 8

__global__ __launch_bounds__(512, 2) void row_kernel(float* __restrict__ out) {
    __shared__ float bufB[16];             // nmax partials
    __shared__ float bufD[16];             // nsum partials
    __shared__ float s_pmin, s_nmax, s_psum;

    const int tid  = threadIdx.x;
    const int lane = tid & 31;
    const int wid  = tid >> 5;
    const int i0   = blockIdx.x * RK_ROWS;

    float loss_acc = 0.0f;
    int   cnt_acc  = 0;

    for (int r = 0; r < RK_ROWS; r++) {
        const int i = i0 + r;

        uint4 hv[2];
        const uint4* hrow = (const uint4*)(g_simh + (size_t)i * NB);
#pragma unroll
        for (int q = 0; q < 2; q++) hv[q] = hrow[q * 512 + tid];

        // warp0: gathered positives (64 floats)
        float p0 = 0.0f, p1 = 0.0f;
        if (wid == 0) {
            p0 = g_pos[(size_t)i * CLS_CAP + lane];
            p1 = g_pos[(size_t)i * CLS_CAP + lane + 32];
        }

        // ---- pass 1: packed row max ----
        __half2 m2 = *(const __half2*)&hv[0].x;
        m2 = __hmax2(m2, *(const __half2*)&hv[0].y);
        m2 = __hmax2(m2, *(const __half2*)&hv[0].z);
        m2 = __hmax2(m2, *(const __half2*)&hv[0].w);
        m2 = __hmax2(m2, *(const __half2*)&hv[1].x);
        m2 = __hmax2(m2, *(const __half2*)&hv[1].y);
        m2 = __hmax2(m2, *(const __half2*)&hv[1].z);
        m2 = __hmax2(m2, *(const __half2*)&hv[1].w);
        float nmax = fmaxf(__low2float(m2), __high2float(m2));
#pragma unroll
        for (int o = 16; o; o >>= 1)
            nmax = fmaxf(nmax, __shfl_xor_sync(0xFFFFFFFFu, nmax, o));
        if (lane == 0) bufB[wid] = nmax;

        if (wid == 0) {
            float pm = fminf(p0, p1);
#pragma unroll
            for (int o = 16; o; o >>= 1)
                pm = fminf(pm, __shfl_xor_sync(0xFFFFFFFFu, pm, o));
            if (lane == 0) s_pmin = pm;
        }
        __syncthreads();
        if (wid == 0) {
            float m = bufB[lane & 15];
#pragma unroll
            for (int o = 8; o; o >>= 1)
                m = fmaxf(m, __shfl_xor_sync(0xFFFFFFFFu, m, o));
            if (lane == 0) s_nmax = m;
        }
        __syncthreads();
        const float pmin = s_pmin;
        nmax = s_nmax;

        // ---- pass 2: nsum with fused threshold; warp0 adds psum ----
        const float tcut = fmaxf(nmax - 0.45f, pmin - C_MARGIN);
        float nsum = 0.0f;
#pragma unroll
        for (int q = 0; q < 2; q++) {
            const uint32_t w[4] = {hv[q].x, hv[q].y, hv[q].z, hv[q].w};
#pragma unroll
            for (int p = 0; p < 4; p++) {
                float2 f = __half22float2(*(const __half2*)&w[p]);
                if (f.x > tcut) nsum += __expf(C_BETA * (f.x - C_BASE));
                if (f.y > tcut) nsum += __expf(C_BETA * (f.y - C_BASE));
            }
        }
#pragma unroll
        for (int o = 16; o; o >>= 1)
            nsum += __shfl_xor_sync(0xFFFFFFFFu, nsum, o);
        if (lane == 0) bufD[wid] = nsum;

        if (wid == 0) {
            float psum = 0.0f;
            if (p0 - C_MARGIN < nmax) psum += __expf(-C_ALPHA * (p0 - C_BASE));
            if (p1 - C_MARGIN < nmax) psum += __expf(-C_ALPHA * (p1 - C_BASE));
#pragma unroll
            for (int o = 16; o; o >>= 1)
                psum += __shfl_xor_sync(0xFFFFFFFFu, psum, o);
            if (lane == 0) s_psum = psum;
        }
        __syncthreads();
        if (wid == 0) {
            float ns = bufD[lane & 15];
#pragma unroll
            for (int o = 8; o; o >>= 1)
                ns += __shfl_xor_sync(0xFFFFFFFFu, ns, o);
            if (lane == 0) {
                const float ps = s_psum;
                if (pmin < INFINITY && ps > 0.0f && ns > 0.0f) {
                    loss_acc += log1pf(ps) / C_ALPHA + log1pf(ns) / C_BETA;
                    cnt_acc++;
                }
            }
        }
        __syncthreads();          // bufs consumed before next row
    }

    if (tid == 0) {
        if (cnt_acc > 0) {
            atomicAdd(&g_loss_sum, loss_acc);
            atomicAdd(&g_valid_cnt, cnt_acc);
        }
        __threadfence();
        const unsigned t = atomicAdd(&g_done, 1u);
        if (t == gridDim.x - 1) {
            const int nv = *((volatile int*)&g_valid_cnt);
            const float ls = *((volatile float*)&g_loss_sum);
            out[0] = ls / (float)(nv > 1 ? nv : 1);
        }
    }
}

// ---------------------------------------------------------------------------
extern "C" void kernel_launch(void* const* d_in, const int* in_sizes, int n_in,
                              void* d_out, int out_size) {
    const float* E      = (const float*)d_in[0];
    const int*   labels = (const int*)d_in[1];
    float*       out    = (float*)d_out;

    cudaFuncSetAttribute(gemm_mma_kernel, cudaFuncAttributeMaxDynamicSharedMemorySize,
                         GEMM_SMEM);

    split_kernel<<<NB * ND / 256, 256>>>(E);
    gemm_mma_kernel<<<NTRI, 256, GEMM_SMEM>>>();
    class_build_kernel<<<NB / 256, 256>>>(labels);
    gather_poison_kernel<<<NB / 8, 256>>>(labels);
    row_kernel<<<NB / RK_ROWS, 512>>>(out);
}